// round 4
// baseline (speedup 1.0000x reference)
#include <cuda_runtime.h>
#include <math.h>

#define Bn   256
#define Ln   512
#define EMB  100
#define HID  128
#define G4   512          // 4*HID
#define TAGS 17
#define BL   (Bn*Ln)      // 131072

// ---------------- scratch (device globals: allocation-free, per rules) ----------------
__device__ float g_xg[2 * BL * G4];     // input-gate preactivations, both dirs
__device__ float g_hf[BL * HID];        // forward hidden states
__device__ float g_hb[BL * HID];        // backward hidden states
__device__ float g_em[BL * TAGS];       // emissions
__device__ float g_WihT[EMB * 1024];    // W_ih transposed, dirs concatenated on cols
__device__ float g_WhhT[2 * HID * G4];  // W_hh transposed (k-major), per dir
__device__ float g_bias[1024];          // b_f ++ b_b

// ---------------- prep: transpose weights ----------------
__global__ void prep_kernel(const float* __restrict__ Wihf, const float* __restrict__ Whhf,
                            const float* __restrict__ bf,   const float* __restrict__ Wihb,
                            const float* __restrict__ Whhb, const float* __restrict__ bb) {
    int i = blockIdx.x * blockDim.x + threadIdx.x;
    int stride = gridDim.x * blockDim.x;
    for (int idx = i; idx < EMB * 1024; idx += stride) {
        int e = idx >> 10, c = idx & 1023, d = c >> 9, j = c & 511;
        g_WihT[idx] = (d ? Wihb : Wihf)[j * EMB + e];
    }
    for (int idx = i; idx < 2 * HID * G4; idx += stride) {
        int d = idx >> 16, r = idx & 65535, k = r >> 9, j = r & 511;
        g_WhhT[idx] = (d ? Whhb : Whhf)[j * HID + k];
    }
    for (int idx = i; idx < 1024; idx += stride) {
        int d = idx >> 9, j = idx & 511;
        g_bias[idx] = (d ? bb : bf)[j];
    }
}

// ---------------- embed + input projection: xg = emb[ids] @ W_ih^T + b ----------------
__global__ void __launch_bounds__(256) xg_kernel(const int* __restrict__ ids,
                                                 const float* __restrict__ emb) {
    __shared__ int   ids_s[64];
    __shared__ float xs[64 * EMB];
    int tid = threadIdx.x;
    int rbase = blockIdx.y * 64;
    int cbase = blockIdx.x * 128;

    if (tid < 64) ids_s[tid] = ids[rbase + tid];
    __syncthreads();
    for (int i = tid; i < 64 * EMB; i += 256) {
        int r = i / EMB, e = i - r * EMB;
        xs[i] = emb[ids_s[r] * EMB + e];
    }
    __syncthreads();

    int tx = tid & 31, ty = tid >> 5;
    int c0 = cbase + tx * 4;
    float acc[8][4];
#pragma unroll
    for (int i = 0; i < 8; i++)
#pragma unroll
        for (int c = 0; c < 4; c++) acc[i][c] = 0.f;

    const float* xrow = xs + (ty * 8) * EMB;
    for (int e = 0; e < EMB; e++) {
        float4 w = *(const float4*)&g_WihT[e * 1024 + c0];
#pragma unroll
        for (int i = 0; i < 8; i++) {
            float xv = xrow[i * EMB + e];
            acc[i][0] += xv * w.x; acc[i][1] += xv * w.y;
            acc[i][2] += xv * w.z; acc[i][3] += xv * w.w;
        }
    }

    int d  = c0 >> 9;
    int jj = c0 & 511;
    float4 bias = *(const float4*)&g_bias[c0];
#pragma unroll
    for (int i = 0; i < 8; i++) {
        int row = rbase + ty * 8 + i;
        float4 o;
        o.x = acc[i][0] + bias.x; o.y = acc[i][1] + bias.y;
        o.z = acc[i][2] + bias.z; o.w = acc[i][3] + bias.w;
        *(float4*)&g_xg[(d * BL + row) * 512 + jj] = o;
    }
}

// ---------------- persistent bidirectional LSTM ----------------
// Grid 128: dir = bid&1, 4 batch elements per CTA, 512 threads.
// KC (runtime): k-rows of W_hh cached in smem; tail rows read via L1/L2.
extern __shared__ float lsmem[];
__device__ __forceinline__ float sigf(float x) { return 1.f / (1.f + expf(-x)); }

__global__ void __launch_bounds__(512, 1) lstm_kernel(int KC) {
    float* Wc    = lsmem;                  // KC*512
    float* hbuf  = lsmem + KC * 512;       // 512
    float* gates = hbuf + 512;             // 2048

    int tid   = threadIdx.x;
    int dir   = blockIdx.x & 1;
    int bbase = (blockIdx.x >> 1) * 4;

    const float* Wt = g_WhhT + dir * (HID * G4);
    for (int i = tid; i < KC * 512; i += 512) Wc[i] = Wt[i];
    hbuf[tid] = 0.f;

    int b = tid >> 7, k = tid & 127;
    float creg = 0.f;
    const float* xgbase = g_xg + dir * (BL * G4);
    float* hout = dir ? g_hb : g_hf;
    __syncthreads();

    for (int s = 0; s < Ln; s++) {
        int tt = dir ? (Ln - 1 - s) : s;
        int j = tid;

        float xg0 = xgbase[((bbase + 0) * Ln + tt) * 512 + j];
        float xg1 = xgbase[((bbase + 1) * Ln + tt) * 512 + j];
        float xg2 = xgbase[((bbase + 2) * Ln + tt) * 512 + j];
        float xg3 = xgbase[((bbase + 3) * Ln + tt) * 512 + j];
        float a0 = 0.f, a1 = 0.f, a2 = 0.f, a3 = 0.f;
#pragma unroll 4
        for (int kk = 0; kk < KC; kk++) {
            float4 h4 = *(const float4*)&hbuf[kk * 4];
            float  w  = Wc[kk * 512 + j];
            a0 += h4.x * w; a1 += h4.y * w; a2 += h4.z * w; a3 += h4.w * w;
        }
        for (int kk = KC; kk < HID; kk++) {
            float4 h4 = *(const float4*)&hbuf[kk * 4];
            float  w  = Wt[kk * 512 + j];   // plain load: keep hot in L1 across steps
            a0 += h4.x * w; a1 += h4.y * w; a2 += h4.z * w; a3 += h4.w * w;
        }
        gates[j]        = a0 + xg0;
        gates[512 + j]  = a1 + xg1;
        gates[1024 + j] = a2 + xg2;
        gates[1536 + j] = a3 + xg3;
        __syncthreads();

        float gi = gates[b * 512 + k];
        float gf = gates[b * 512 + 128 + k];
        float gg = gates[b * 512 + 256 + k];
        float go = gates[b * 512 + 384 + k];
        creg = sigf(gf) * creg + sigf(gi) * tanhf(gg);
        float h = sigf(go) * tanhf(creg);
        hbuf[k * 4 + b] = h;
        hout[((bbase + b) * Ln + tt) * HID + k] = h;
        __syncthreads();
    }
}

// ---------------- FC: emissions = [h_f, h_b] @ fc_W^T + fc_b ----------------
__global__ void __launch_bounds__(256) fc_kernel(const float* __restrict__ fcW,
                                                 const float* __restrict__ fcb) {
    int warp = (blockIdx.x * blockDim.x + threadIdx.x) >> 5;
    int lane = threadIdx.x & 31;
    if (warp >= BL) return;
    float4 hf = *(const float4*)&g_hf[warp * HID + lane * 4];
    float4 hb = *(const float4*)&g_hb[warp * HID + lane * 4];
#pragma unroll
    for (int t = 0; t < TAGS; t++) {
        float4 wf = *(const float4*)&fcW[t * 256 + lane * 4];
        float4 wb = *(const float4*)&fcW[t * 256 + 128 + lane * 4];
        float s = hf.x * wf.x + hf.y * wf.y + hf.z * wf.z + hf.w * wf.w
                + hb.x * wb.x + hb.y * wb.y + hb.z * wb.z + hb.w * wb.w;
#pragma unroll
        for (int off = 16; off; off >>= 1) s += __shfl_xor_sync(0xffffffffu, s, off);
        if (lane == 0) g_em[warp * TAGS + t] = s + fcb[t];
    }
}

// ---------------- Viterbi: one warp per batch element; FLOAT32 output ----------------
__global__ void __launch_bounds__(128) viterbi_kernel(const int* __restrict__ ids,
                                                      const float* __restrict__ trans,
                                                      const float* __restrict__ start_t,
                                                      const float* __restrict__ end_t,
                                                      float* __restrict__ out) {
    __shared__ unsigned char hist[4][Ln * 20];
    int w = threadIdx.x >> 5, lane = threadIdx.x & 31;
    int b = blockIdx.x * 4 + w;
    const float NEG = -3e38f;

    float tcol[TAGS];
#pragma unroll
    for (int i = 0; i < TAGS; i++)
        tcol[i] = (lane < TAGS) ? trans[i * TAGS + lane] : 0.f;

    const float* emrow = g_em + b * Ln * TAGS;
    const int*   idrow = ids + b * Ln;

    float score = (lane < TAGS) ? start_t[lane] + emrow[lane] : NEG;

    for (int t = 1; t < Ln; t++) {
        float em = (lane < TAGS) ? emrow[t * TAGS + lane] : 0.f;
        int mask = (idrow[t] != 0);
        float best = NEG; int bi = 1;     // bi=1 only survives if all cands NaN (diagnostic)
#pragma unroll
        for (int i = 0; i < TAGS; i++) {
            float si = __shfl_sync(0xffffffffu, score, i);
            float v = si + tcol[i];
            if (v > best) { best = v; bi = i; }   // first max wins (matches jnp.argmax)
        }
        int idx;
        if (mask) { if (lane < TAGS) score = best + em; idx = bi; }
        else      { idx = lane; }                  // identity backpointer on pads
        if (lane < TAGS) hist[w][t * 20 + lane] = (unsigned char)idx;
    }

    float fin = (lane < TAGS) ? score + end_t[lane] : NEG;
    int fid = lane;
#pragma unroll
    for (int off = 16; off; off >>= 1) {
        float ov = __shfl_xor_sync(0xffffffffu, fin, off);
        int   oi = __shfl_xor_sync(0xffffffffu, fid, off);
        if (ov > fin || (ov == fin && oi < fid)) { fin = ov; fid = oi; }
    }
    __syncwarp();

    if (lane == 0) {
        int tag = fid;
        float* orow = out + b * Ln;
        orow[Ln - 1] = (idrow[Ln - 1] != 0) ? (float)tag : 0.f;
        for (int t = Ln - 2; t >= 0; t--) {
            tag = hist[w][(t + 1) * 20 + tag];
            orow[t] = (idrow[t] != 0) ? (float)tag : 0.f;
        }
    }
}

// ---------------- launch ----------------
extern "C" void kernel_launch(void* const* d_in, const int* in_sizes, int n_in,
                              void* d_out, int out_size) {
    // Map inputs by element count (robust; proven equivalent to dict order).
    const void* p[13];
    for (int i = 0; i < 13; i++) p[i] = 0;
    int c51200 = 0, c65536 = 0, c512 = 0, c17 = 0;
    for (int i = 0; i < n_in; i++) {
        switch (in_sizes[i]) {
            case 131072:  p[0] = d_in[i]; break;                       // input_ids
            case 3000000: p[1] = d_in[i]; break;                       // emb
            case 51200:   p[(c51200++ == 0) ? 2 : 5] = d_in[i]; break; // W_ih_{f,b}
            case 65536:   p[(c65536++ == 0) ? 3 : 6] = d_in[i]; break; // W_hh_{f,b}
            case 512:     p[(c512++   == 0) ? 4 : 7] = d_in[i]; break; // b_{f,b}
            case 4352:    p[8]  = d_in[i]; break;                      // fc_W
            case 289:     p[10] = d_in[i]; break;                      // trans
            case 17: {
                int k = c17++;
                p[(k == 0) ? 9 : ((k == 1) ? 11 : 12)] = d_in[i];      // fc_b, start_t, end_t
                break;
            }
            default: break;
        }
    }
    const int*   input_ids = (const int*)  p[0];
    const float* emb       = (const float*)p[1];
    const float* Wihf      = (const float*)p[2];
    const float* Whhf      = (const float*)p[3];
    const float* bf        = (const float*)p[4];
    const float* Wihb      = (const float*)p[5];
    const float* Whhb      = (const float*)p[6];
    const float* bb        = (const float*)p[7];
    const float* fcW       = (const float*)p[8];
    const float* fcb       = (const float*)p[9];
    const float* trans     = (const float*)p[10];
    const float* startt    = (const float*)p[11];
    const float* endt      = (const float*)p[12];
    float* out = (float*)d_out;

    prep_kernel<<<64, 256>>>(Wihf, Whhf, bf, Wihb, Whhb, bb);
    xg_kernel<<<dim3(8, 2048), 256>>>(input_ids, emb);

    // Size the smem W_hh cache; fall back to 48KB-static-legal KC if opt-in rejected.
    int dev = 0;
    cudaGetDevice(&dev);
    int maxS = 0;
    cudaDeviceGetAttribute(&maxS, cudaDevAttrMaxSharedMemoryPerBlockOptin, dev);
    int KC = (maxS / 4 - 2560 - 128) / 512;
    if (KC > HID) KC = HID;
    if (KC < 0)   KC = 0;
    int lsmem_bytes = (KC * 512 + 2560) * (int)sizeof(float);
    if (lsmem_bytes > 48 * 1024) {
        if (cudaFuncSetAttribute(lstm_kernel, cudaFuncAttributeMaxDynamicSharedMemorySize,
                                 lsmem_bytes) != cudaSuccess) {
            KC = 18;                                   // 47104 bytes, under default 48KB
            lsmem_bytes = (KC * 512 + 2560) * (int)sizeof(float);
        }
    }
    lstm_kernel<<<128, 512, lsmem_bytes>>>(KC);

    fc_kernel<<<16384, 256>>>(fcW, fcb);
    viterbi_kernel<<<64, 128>>>(input_ids, trans, startt, endt, out);
}

// round 5
// speedup vs baseline: 1.0259x; 1.0259x over previous
#include <cuda_runtime.h>
#include <math.h>
#include <stdint.h>

#define Bn   256
#define Ln   512
#define EMB  100
#define HID  128
#define G4   512          // 4*HID
#define TAGS 17
#define BL   (Bn*Ln)      // 131072
#define KC   104          // W_hh k-rows cached in smem (compile-time)
#define KTAIL (HID - KC)  // 24 k-rows cached in registers

// ---------------- scratch (device globals: allocation-free, per rules) ----------------
__device__ float g_xg[2 * BL * G4];     // input-gate preactivations, both dirs
__device__ float g_hf[BL * HID];        // forward hidden states
__device__ float g_hb[BL * HID];        // backward hidden states
__device__ float g_em[BL * TAGS];       // emissions
__device__ float g_WihT[EMB * 1024];    // W_ih transposed, dirs concatenated on cols
__device__ float g_WhhT[2 * HID * G4];  // W_hh transposed (k-major), per dir
__device__ float g_bias[1024];          // b_f ++ b_b

// ---------------- packed f32x2 helpers ----------------
__device__ __forceinline__ uint64_t pack2(float lo, float hi) {
    uint64_t r;
    asm("mov.b64 %0, {%1, %2};" : "=l"(r) : "f"(lo), "f"(hi));
    return r;
}
__device__ __forceinline__ float2 unpack2(uint64_t v) {
    float lo, hi;
    asm("mov.b64 {%0, %1}, %2;" : "=f"(lo), "=f"(hi) : "l"(v));
    return make_float2(lo, hi);
}
__device__ __forceinline__ void ffma2(uint64_t& acc, uint64_t a, uint64_t b) {
    asm("fma.rn.f32x2 %0, %1, %2, %0;" : "+l"(acc) : "l"(a), "l"(b));
}

// ---------------- prep: transpose weights ----------------
__global__ void prep_kernel(const float* __restrict__ Wihf, const float* __restrict__ Whhf,
                            const float* __restrict__ bf,   const float* __restrict__ Wihb,
                            const float* __restrict__ Whhb, const float* __restrict__ bb) {
    int i = blockIdx.x * blockDim.x + threadIdx.x;
    int stride = gridDim.x * blockDim.x;
    for (int idx = i; idx < EMB * 1024; idx += stride) {
        int e = idx >> 10, c = idx & 1023, d = c >> 9, j = c & 511;
        g_WihT[idx] = (d ? Wihb : Wihf)[j * EMB + e];
    }
    for (int idx = i; idx < 2 * HID * G4; idx += stride) {
        int d = idx >> 16, r = idx & 65535, k = r >> 9, j = r & 511;
        g_WhhT[idx] = (d ? Whhb : Whhf)[j * HID + k];
    }
    for (int idx = i; idx < 1024; idx += stride) {
        int d = idx >> 9, j = idx & 511;
        g_bias[idx] = (d ? bb : bf)[j];
    }
}

// ---------------- embed + input projection: xg = emb[ids] @ W_ih^T + b (f32x2) --------
__global__ void __launch_bounds__(256) xg_kernel(const int* __restrict__ ids,
                                                 const float* __restrict__ emb) {
    __shared__ int   ids_s[64];
    __shared__ float xs[64 * EMB];
    int tid = threadIdx.x;
    int rbase = blockIdx.y * 64;
    int cbase = blockIdx.x * 128;

    if (tid < 64) ids_s[tid] = ids[rbase + tid];
    __syncthreads();
    for (int i = tid; i < 64 * EMB; i += 256) {
        int r = i / EMB, e = i - r * EMB;
        xs[i] = emb[ids_s[r] * EMB + e];
    }
    __syncthreads();

    int tx = tid & 31, ty = tid >> 5;
    int c0 = cbase + tx * 4;

    uint64_t accA[8], accB[8];                 // (c0,c1) and (c2,c3) pairs per row
    uint64_t z = pack2(0.f, 0.f);
#pragma unroll
    for (int i = 0; i < 8; i++) { accA[i] = z; accB[i] = z; }

    const float* xrow = xs + (ty * 8) * EMB;
    for (int e = 0; e < EMB; e++) {
        ulonglong2 w2 = *(const ulonglong2*)&g_WihT[e * 1024 + c0];
#pragma unroll
        for (int i = 0; i < 8; i++) {
            float xv = xrow[i * EMB + e];
            uint64_t xx = pack2(xv, xv);
            ffma2(accA[i], xx, w2.x);
            ffma2(accB[i], xx, w2.y);
        }
    }

    int d  = c0 >> 9;
    int jj = c0 & 511;
    float4 bias = *(const float4*)&g_bias[c0];
#pragma unroll
    for (int i = 0; i < 8; i++) {
        int row = rbase + ty * 8 + i;
        float2 vA = unpack2(accA[i]);
        float2 vB = unpack2(accB[i]);
        float4 o;
        o.x = vA.x + bias.x; o.y = vA.y + bias.y;
        o.z = vB.x + bias.z; o.w = vB.y + bias.w;
        *(float4*)&g_xg[(d * BL + row) * 512 + jj] = o;
    }
}

// ---------------- persistent bidirectional LSTM (f32x2 + prefetch) ----------------
// Grid 128: dir = bid&1, 4 batch elements per CTA, 512 threads.
extern __shared__ float lsmem[];
__device__ __forceinline__ float sigf(float x) { return 1.f / (1.f + expf(-x)); }

__global__ void __launch_bounds__(512, 1) lstm_kernel() {
    float* Wc    = lsmem;                  // KC*512
    float* hbuf  = lsmem + KC * 512;       // 512   (16B-aligned: KC*512*4 % 16 == 0)
    float* gates = hbuf + 512;             // 2048

    int tid   = threadIdx.x;
    int dir   = blockIdx.x & 1;
    int bbase = (blockIdx.x >> 1) * 4;

    const float* Wt = g_WhhT + dir * (HID * G4);
    for (int i = tid; i < KC * 512; i += 512) Wc[i] = Wt[i];
    hbuf[tid] = 0.f;

    // tail W rows in per-thread registers
    float wtail[KTAIL];
#pragma unroll
    for (int kk = 0; kk < KTAIL; kk++)
        wtail[kk] = Wt[(KC + kk) * 512 + tid];

    int b = tid >> 7, k = tid & 127;
    float creg = 0.f;
    const float* xgbase = g_xg + dir * (BL * G4);
    float* hout = dir ? g_hb : g_hf;

    int tt0 = dir ? (Ln - 1) : 0;
    int step_dt = dir ? -512 : 512;
    int off0 = ((bbase + 0) * Ln + tt0) * 512 + tid;
    int off1 = ((bbase + 1) * Ln + tt0) * 512 + tid;
    int off2 = ((bbase + 2) * Ln + tt0) * 512 + tid;
    int off3 = ((bbase + 3) * Ln + tt0) * 512 + tid;

    float cxg0 = xgbase[off0], cxg1 = xgbase[off1];
    float cxg2 = xgbase[off2], cxg3 = xgbase[off3];
    __syncthreads();

    const float* wp = Wc + tid;
    for (int s = 0; s < Ln; s++) {
        // prefetch next step's xg (consumed next iteration; hidden under gate loop)
        float nxg0 = 0.f, nxg1 = 0.f, nxg2 = 0.f, nxg3 = 0.f;
        if (s + 1 < Ln) {
            nxg0 = xgbase[off0 + step_dt];
            nxg1 = xgbase[off1 + step_dt];
            nxg2 = xgbase[off2 + step_dt];
            nxg3 = xgbase[off3 + step_dt];
        }

        uint64_t a01 = pack2(cxg0, cxg1);
        uint64_t a23 = pack2(cxg2, cxg3);
#pragma unroll 8
        for (int kk = 0; kk < KC; kk++) {
            ulonglong2 hh = *(const ulonglong2*)(hbuf + kk * 4);  // (b0,b1) | (b2,b3)
            float w = wp[kk * 512];
            uint64_t ww = pack2(w, w);
            ffma2(a01, hh.x, ww);
            ffma2(a23, hh.y, ww);
        }
#pragma unroll
        for (int kk = 0; kk < KTAIL; kk++) {
            ulonglong2 hh = *(const ulonglong2*)(hbuf + (KC + kk) * 4);
            uint64_t ww = pack2(wtail[kk], wtail[kk]);
            ffma2(a01, hh.x, ww);
            ffma2(a23, hh.y, ww);
        }
        float2 g01 = unpack2(a01);
        float2 g23 = unpack2(a23);
        gates[tid]        = g01.x;
        gates[512 + tid]  = g01.y;
        gates[1024 + tid] = g23.x;
        gates[1536 + tid] = g23.y;
        __syncthreads();

        // cell update for (b, k)
        float gi = gates[b * 512 + k];
        float gf = gates[b * 512 + 128 + k];
        float gg = gates[b * 512 + 256 + k];
        float go = gates[b * 512 + 384 + k];
        creg = sigf(gf) * creg + sigf(gi) * tanhf(gg);
        float h = sigf(go) * tanhf(creg);
        hbuf[k * 4 + b] = h;
        int tt = dir ? (Ln - 1 - s) : s;
        hout[((bbase + b) * Ln + tt) * HID + k] = h;
        __syncthreads();

        cxg0 = nxg0; cxg1 = nxg1; cxg2 = nxg2; cxg3 = nxg3;
        off0 += step_dt; off1 += step_dt; off2 += step_dt; off3 += step_dt;
    }
}

// ---------------- FC: emissions = [h_f, h_b] @ fc_W^T + fc_b ----------------
__global__ void __launch_bounds__(256) fc_kernel(const float* __restrict__ fcW,
                                                 const float* __restrict__ fcb) {
    int warp = (blockIdx.x * blockDim.x + threadIdx.x) >> 5;
    int lane = threadIdx.x & 31;
    if (warp >= BL) return;
    float4 hf = *(const float4*)&g_hf[warp * HID + lane * 4];
    float4 hb = *(const float4*)&g_hb[warp * HID + lane * 4];
#pragma unroll
    for (int t = 0; t < TAGS; t++) {
        float4 wf = *(const float4*)&fcW[t * 256 + lane * 4];
        float4 wb = *(const float4*)&fcW[t * 256 + 128 + lane * 4];
        float s = hf.x * wf.x + hf.y * wf.y + hf.z * wf.z + hf.w * wf.w
                + hb.x * wb.x + hb.y * wb.y + hb.z * wb.z + hb.w * wb.w;
#pragma unroll
        for (int off = 16; off; off >>= 1) s += __shfl_xor_sync(0xffffffffu, s, off);
        if (lane == 0) g_em[warp * TAGS + t] = s + fcb[t];
    }
}

// ---------------- Viterbi: one warp per batch element; float32 output ----------------
__global__ void __launch_bounds__(128) viterbi_kernel(const int* __restrict__ ids,
                                                      const float* __restrict__ trans,
                                                      const float* __restrict__ start_t,
                                                      const float* __restrict__ end_t,
                                                      float* __restrict__ out) {
    __shared__ unsigned char hist[4][Ln * 20];
    int w = threadIdx.x >> 5, lane = threadIdx.x & 31;
    int b = blockIdx.x * 4 + w;
    const float NEG = -3e38f;

    float tcol[TAGS];
#pragma unroll
    for (int i = 0; i < TAGS; i++)
        tcol[i] = (lane < TAGS) ? trans[i * TAGS + lane] : 0.f;

    const float* emrow = g_em + b * Ln * TAGS;
    const int*   idrow = ids + b * Ln;

    float score = (lane < TAGS) ? start_t[lane] + emrow[lane] : NEG;

    for (int t = 1; t < Ln; t++) {
        float em = (lane < TAGS) ? emrow[t * TAGS + lane] : 0.f;
        int mask = (idrow[t] != 0);
        float best = NEG; int bi = 0;
#pragma unroll
        for (int i = 0; i < TAGS; i++) {
            float si = __shfl_sync(0xffffffffu, score, i);
            float v = si + tcol[i];
            if (v > best) { best = v; bi = i; }   // first max wins (matches jnp.argmax)
        }
        int idx;
        if (mask) { if (lane < TAGS) score = best + em; idx = bi; }
        else      { idx = lane; }                  // identity backpointer on pads
        if (lane < TAGS) hist[w][t * 20 + lane] = (unsigned char)idx;
    }

    float fin = (lane < TAGS) ? score + end_t[lane] : NEG;
    int fid = lane;
#pragma unroll
    for (int off = 16; off; off >>= 1) {
        float ov = __shfl_xor_sync(0xffffffffu, fin, off);
        int   oi = __shfl_xor_sync(0xffffffffu, fid, off);
        if (ov > fin || (ov == fin && oi < fid)) { fin = ov; fid = oi; }
    }
    __syncwarp();

    if (lane == 0) {
        int tag = fid;
        float* orow = out + b * Ln;
        orow[Ln - 1] = (idrow[Ln - 1] != 0) ? (float)tag : 0.f;
        for (int t = Ln - 2; t >= 0; t--) {
            tag = hist[w][(t + 1) * 20 + tag];
            orow[t] = (idrow[t] != 0) ? (float)tag : 0.f;
        }
    }
}

// ---------------- launch ----------------
extern "C" void kernel_launch(void* const* d_in, const int* in_sizes, int n_in,
                              void* d_out, int out_size) {
    // Map inputs by element count (robust; proven correct in Round 4).
    const void* p[13];
    for (int i = 0; i < 13; i++) p[i] = 0;
    int c51200 = 0, c65536 = 0, c512 = 0, c17 = 0;
    for (int i = 0; i < n_in; i++) {
        switch (in_sizes[i]) {
            case 131072:  p[0] = d_in[i]; break;                       // input_ids
            case 3000000: p[1] = d_in[i]; break;                       // emb
            case 51200:   p[(c51200++ == 0) ? 2 : 5] = d_in[i]; break; // W_ih_{f,b}
            case 65536:   p[(c65536++ == 0) ? 3 : 6] = d_in[i]; break; // W_hh_{f,b}
            case 512:     p[(c512++   == 0) ? 4 : 7] = d_in[i]; break; // b_{f,b}
            case 4352:    p[8]  = d_in[i]; break;                      // fc_W
            case 289:     p[10] = d_in[i]; break;                      // trans
            case 17: {
                int k = c17++;
                p[(k == 0) ? 9 : ((k == 1) ? 11 : 12)] = d_in[i];      // fc_b, start_t, end_t
                break;
            }
            default: break;
        }
    }
    const int*   input_ids = (const int*)  p[0];
    const float* emb       = (const float*)p[1];
    const float* Wihf      = (const float*)p[2];
    const float* Whhf      = (const float*)p[3];
    const float* bf        = (const float*)p[4];
    const float* Wihb      = (const float*)p[5];
    const float* Whhb      = (const float*)p[6];
    const float* bb        = (const float*)p[7];
    const float* fcW       = (const float*)p[8];
    const float* fcb       = (const float*)p[9];
    const float* trans     = (const float*)p[10];
    const float* startt    = (const float*)p[11];
    const float* endt      = (const float*)p[12];
    float* out = (float*)d_out;

    prep_kernel<<<64, 256>>>(Wihf, Whhf, bf, Wihb, Whhb, bb);
    xg_kernel<<<dim3(8, 2048), 256>>>(input_ids, emb);

    const int lsmem_bytes = (KC * 512 + 2560) * (int)sizeof(float); // 223232
    cudaFuncSetAttribute(lstm_kernel, cudaFuncAttributeMaxDynamicSharedMemorySize,
                         lsmem_bytes);
    lstm_kernel<<<128, 512, lsmem_bytes>>>();

    fc_kernel<<<16384, 256>>>(fcW, fcb);
    viterbi_kernel<<<64, 128>>>(input_ids, trans, startt, endt, out);
}